// round 10
// baseline (speedup 1.0000x reference)
#include <cuda_runtime.h>
#include <cuda_bf16.h>

// scatter_mean: out[m, c] = sum_{i: idx[i]==m} in[i, c] / max(count_m, 1)
// N = 4,000,000 rows, C = 16 channels fp32, M = 500,000 segments, idx int32.
//
// Structure (validated R6-R9):
//   HW memsets (~5us) -> quad-REDG scatter (per-SM reduction-command floor,
//   20M lanes ~= 77us; v4.f32 is the max atomic width, TMA bulk-reduce shares
//   the same command path) -> finalize (latency-tuned, ~10us).

#define CHANNELS 16
#define MAX_SEGMENTS 500000

__device__ float g_counts[MAX_SEGMENTS];

// ---------------------------------------------------------------------------
// Scatter-add, 4 lanes per row (quad-per-row). Each lane: 1 float4 load +
// 1 red.global.add.v4.f32 (16B); quad covers one 64B destination row.
// Lane 0 of each quad adds the count.
// ---------------------------------------------------------------------------
__global__ void __launch_bounds__(256, 8)
dve_scatter_kernel(const float4* __restrict__ in,
                   const int* __restrict__ idx,
                   float4* __restrict__ sums4,
                   int n) {
    int t = blockIdx.x * blockDim.x + threadIdx.x;   // [0, 4n)
    int row = t >> 2;
    int q = t & 3;
    if (row >= n) return;

    int s = __ldg(idx + row);                         // quad lanes share a sector
    float4 v = __ldg(in + (size_t)row * 4 + q);       // warp reads 8 rows = 512B

    float4* p = sums4 + (size_t)s * 4 + q;            // quad covers one 64B row
    asm volatile("red.global.add.v4.f32 [%0], {%1, %2, %3, %4};"
                 :: "l"(p), "f"(v.x), "f"(v.y), "f"(v.z), "f"(v.w) : "memory");

    if (q == 0)
        atomicAdd(&g_counts[s], 1.0f);
}

// ---------------------------------------------------------------------------
// Finalize: each thread scales 2 CONSECUTIVE float4s of ONE segment
// (segment = t>>1). One count load per thread (halved vs R9), both data
// loads in the same 128B line, warp's count loads span one 64B region.
// 1M threads keep occupancy-side latency hiding (R5/R9 calibration).
// ---------------------------------------------------------------------------
__global__ void __launch_bounds__(256, 8)
dve_finalize_kernel(float4* __restrict__ out, int total4) {
    int t = blockIdx.x * blockDim.x + threadIdx.x;   // [0, total4/2)
    int e = t * 2;
    if (e >= total4) return;

    float cnt = g_counts[t >> 1];                     // 2 threads per segment
    float4 v0 = out[e];
    float4 v1 = out[e + 1];
    float inv = 1.0f / fmaxf(cnt, 1.0f);

    v0.x *= inv; v0.y *= inv; v0.z *= inv; v0.w *= inv;
    v1.x *= inv; v1.y *= inv; v1.z *= inv; v1.w *= inv;
    out[e] = v0;
    out[e + 1] = v1;
}

// ---------------------------------------------------------------------------
// Launch
// ---------------------------------------------------------------------------
extern "C" void kernel_launch(void* const* d_in, const int* in_sizes, int n_in,
                              void* d_out, int out_size) {
    const float4* in = (const float4*)d_in[0];   // [N, 16] fp32
    const int* idx = (const int*)d_in[1];        // [N] int32
    float* out = (float*)d_out;                  // [M, 16] fp32

    int n = in_sizes[0] / CHANNELS;   // 4,000,000
    int m = out_size / CHANNELS;      // 500,000

    // Zero sums + counts via HW memset nodes (graph-capturable, no alloc).
    void* counts_ptr = nullptr;
    cudaGetSymbolAddress(&counts_ptr, g_counts);
    cudaMemsetAsync(d_out, 0, (size_t)out_size * sizeof(float), 0);
    cudaMemsetAsync(counts_ptr, 0, (size_t)m * sizeof(float), 0);

    {
        int threads = 256;
        long long total = (long long)n * 4;
        int blocks = (int)((total + threads - 1) / threads);
        dve_scatter_kernel<<<blocks, threads>>>(in, idx, (float4*)out, n);
    }
    {
        int threads = 256;
        int total4 = m * 4;                       // 2,000,000 float4s
        int nthreads = total4 / 2;                // 1,000,000
        int blocks = (nthreads + threads - 1) / threads;  // 3907
        dve_finalize_kernel<<<blocks, threads>>>((float4*)out, total4);
    }
}

// round 11
// speedup vs baseline: 1.0258x; 1.0258x over previous
#include <cuda_runtime.h>
#include <cuda_bf16.h>

// scatter_mean: out[m, c] = sum_{i: idx[i]==m} in[i, c] / max(count_m, 1)
// N = 4,000,000 rows, C = 16 channels fp32, M = 500,000 segments, idx int32.
//
// Structure (validated R6-R10):
//   HW memsets (~5us) -> quad-REDG scatter (per-SM reduction-LANE floor,
//   20M lanes ~= 77us; v4.f32 is max atomic width; TMA bulk-reduce shares the
//   command path; count-merging doesn't reduce lanes) -> finalize (strided,
//   fully-coalesced, MLP=3).
// R10 lesson: consecutive-per-thread layouts break per-instruction
// coalescing; always grid-stride.

#define CHANNELS 16
#define MAX_SEGMENTS 500000

__device__ float g_counts[MAX_SEGMENTS];

// ---------------------------------------------------------------------------
// Scatter-add, 4 lanes per row (quad-per-row). Each lane: 1 float4 load +
// 1 red.global.add.v4.f32 (16B); quad covers one 64B destination row.
// Lane 0 of each quad adds the count.
// ---------------------------------------------------------------------------
__global__ void __launch_bounds__(256, 8)
dve_scatter_kernel(const float4* __restrict__ in,
                   const int* __restrict__ idx,
                   float4* __restrict__ sums4,
                   int n) {
    int t = blockIdx.x * blockDim.x + threadIdx.x;   // [0, 4n)
    int row = t >> 2;
    int q = t & 3;
    if (row >= n) return;

    int s = __ldg(idx + row);                         // quad lanes share a sector
    float4 v = __ldg(in + (size_t)row * 4 + q);       // warp reads 8 rows = 512B

    float4* p = sums4 + (size_t)s * 4 + q;            // quad covers one 64B row
    asm volatile("red.global.add.v4.f32 [%0], {%1, %2, %3, %4};"
                 :: "l"(p), "f"(v.x), "f"(v.y), "f"(v.z), "f"(v.w) : "memory");

    if (q == 0)
        atomicAdd(&g_counts[s], 1.0f);
}

// ---------------------------------------------------------------------------
// Finalize: 3 grid-strided float4s per thread, all loads (3 data + 3 count)
// issued before any dependent math -> MLP=6 outstanding requests against
// ~234cyc L2 latency. Every LDG/STG is warp-contiguous (fully coalesced).
// ~667K threads keeps 18x oversubscription for occupancy-side hiding.
// ---------------------------------------------------------------------------
__global__ void __launch_bounds__(256, 8)
dve_finalize_kernel(float4* __restrict__ out, int total4) {
    int stride = gridDim.x * blockDim.x;
    int t0 = blockIdx.x * blockDim.x + threadIdx.x;
    int t1 = t0 + stride;
    int t2 = t1 + stride;

    if (t2 < total4) {
        float c0 = g_counts[t0 >> 2];
        float c1 = g_counts[t1 >> 2];
        float c2 = g_counts[t2 >> 2];
        float4 v0 = out[t0];
        float4 v1 = out[t1];
        float4 v2 = out[t2];
        float i0 = 1.0f / fmaxf(c0, 1.0f);
        float i1 = 1.0f / fmaxf(c1, 1.0f);
        float i2 = 1.0f / fmaxf(c2, 1.0f);
        v0.x *= i0; v0.y *= i0; v0.z *= i0; v0.w *= i0;
        v1.x *= i1; v1.y *= i1; v1.z *= i1; v1.w *= i1;
        v2.x *= i2; v2.y *= i2; v2.z *= i2; v2.w *= i2;
        out[t0] = v0;
        out[t1] = v1;
        out[t2] = v2;
    } else {
        for (int t = t0; t < total4; t += stride) {
            float inv = 1.0f / fmaxf(g_counts[t >> 2], 1.0f);
            float4 v = out[t];
            v.x *= inv; v.y *= inv; v.z *= inv; v.w *= inv;
            out[t] = v;
        }
    }
}

// ---------------------------------------------------------------------------
// Launch
// ---------------------------------------------------------------------------
extern "C" void kernel_launch(void* const* d_in, const int* in_sizes, int n_in,
                              void* d_out, int out_size) {
    const float4* in = (const float4*)d_in[0];   // [N, 16] fp32
    const int* idx = (const int*)d_in[1];        // [N] int32
    float* out = (float*)d_out;                  // [M, 16] fp32

    int n = in_sizes[0] / CHANNELS;   // 4,000,000
    int m = out_size / CHANNELS;      // 500,000

    // Zero sums + counts via HW memset nodes (graph-capturable, no alloc).
    void* counts_ptr = nullptr;
    cudaGetSymbolAddress(&counts_ptr, g_counts);
    cudaMemsetAsync(d_out, 0, (size_t)out_size * sizeof(float), 0);
    cudaMemsetAsync(counts_ptr, 0, (size_t)m * sizeof(float), 0);

    {
        int threads = 256;
        long long total = (long long)n * 4;
        int blocks = (int)((total + threads - 1) / threads);
        dve_scatter_kernel<<<blocks, threads>>>(in, idx, (float4*)out, n);
    }
    {
        int threads = 256;
        int total4 = m * 4;                           // 2,000,000 float4s
        int nthreads = (total4 + 2) / 3;              // ~666,667
        int blocks = (nthreads + threads - 1) / threads;  // 2605
        dve_finalize_kernel<<<blocks, threads>>>((float4*)out, total4);
    }
}